// round 2
// baseline (speedup 1.0000x reference)
#include <cuda_runtime.h>
#include <math.h>

#define T_TOKENS 8192
#define HDIM 1024
#define IDIM 512
#define NEXP 32
#define TOPK 4
#define TILE_M 64
#define XS_LD 68
#define HS_LD 68

// ---------------- device scratch (static allocations only) ----------------
__device__ float g_scratch[(size_t)T_TOKENS * TOPK * HDIM]; // 128 MB partials
__device__ int   g_top_idx[T_TOKENS * TOPK];
__device__ float g_top_wt [T_TOKENS * TOPK];
__device__ int   g_cnt[NEXP];
__device__ int   g_etok[NEXP * T_TOKENS];   // (token<<2)|slot
__device__ float g_ewt [NEXP * T_TOKENS];

// ---------------- router: logits -> top-4 (idx, normalized weight) --------
__global__ void router_kernel(const float* __restrict__ x,
                              const float* __restrict__ gw) {
    __shared__ float xs[8][HDIM];
    int t0 = blockIdx.x * 8;
    for (int i = threadIdx.x; i < 8 * (HDIM / 4); i += blockDim.x) {
        int row = i >> 8;           // HDIM/4 == 256
        int c4  = i & 255;
        ((float4*)xs[row])[c4] = ((const float4*)(x + (size_t)(t0 + row) * HDIM))[c4];
    }
    __syncthreads();

    int w = threadIdx.x >> 5;
    int lane = threadIdx.x & 31;
    int t = t0 + w;
    const float* xr = xs[w];

    float myLogit = 0.f;
    for (int e = 0; e < NEXP; ++e) {
        const float* wr = gw + (size_t)e * HDIM;
        float s = 0.f;
        #pragma unroll 8
        for (int j = lane; j < HDIM; j += 32) s += xr[j] * wr[j];
        #pragma unroll
        for (int off = 16; off; off >>= 1) s += __shfl_xor_sync(0xffffffffu, s, off);
        if (lane == e) myLogit = s;
    }

    // warp top-4 (each lane holds one expert's logit), tie-break lower index
    float v = myLogit;
    float selv[TOPK];
    int   seli[TOPK];
    #pragma unroll
    for (int k = 0; k < TOPK; ++k) {
        float bv = v; int bi = lane;
        #pragma unroll
        for (int off = 16; off; off >>= 1) {
            float ov = __shfl_xor_sync(0xffffffffu, bv, off);
            int   oi = __shfl_xor_sync(0xffffffffu, bi, off);
            if (ov > bv || (ov == bv && oi < bi)) { bv = ov; bi = oi; }
        }
        selv[k] = bv; seli[k] = bi;
        if (lane == bi) v = -1e30f;
    }

    if (lane == 0) {
        float m = selv[0];
        float ew[TOPK];
        float sum = 0.f;
        #pragma unroll
        for (int k = 0; k < TOPK; ++k) { ew[k] = expf(selv[k] - m); sum += ew[k]; }
        float inv = 1.f / sum;
        #pragma unroll
        for (int k = 0; k < TOPK; ++k) {
            g_top_idx[t * TOPK + k] = seli[k];
            g_top_wt [t * TOPK + k] = ew[k] * inv;
        }
    }
}

__global__ void zero_cnt_kernel() {
    if (threadIdx.x < NEXP) g_cnt[threadIdx.x] = 0;
}

__global__ void scatter_kernel() {
    int t = blockIdx.x * blockDim.x + threadIdx.x;
    if (t >= T_TOKENS) return;
    #pragma unroll
    for (int k = 0; k < TOPK; ++k) {
        int e = g_top_idx[t * TOPK + k];
        int pos = atomicAdd(&g_cnt[e], 1);
        g_etok[e * T_TOKENS + pos] = (t << 2) | k;
        g_ewt [e * T_TOKENS + pos] = g_top_wt[t * TOPK + k];
    }
}

// ---------------- expert MLP: gather tile -> SwiGLU -> down-proj ----------
__global__ void __launch_bounds__(256, 1)
expert_kernel(const float* __restrict__ x,
              const float* __restrict__ wg,
              const float* __restrict__ wu,
              const float* __restrict__ wd) {
    extern __shared__ float sm[];
    float* hs  = sm;                          // [IDIM][HS_LD]
    float* xs  = hs  + IDIM * HS_LD;          // [32][XS_LD]  (k-major, m contiguous)
    float* ws0 = xs  + 32 * XS_LD;            // [32][128]
    float* ws1 = ws0 + 32 * 128;              // [32][128]

    __shared__ int   toks [TILE_M];
    __shared__ int   slots[TILE_M];
    __shared__ float wts  [TILE_M];

    int e = blockIdx.y;
    int ne = g_cnt[e];
    int start = blockIdx.x * TILE_M;
    if (start >= ne) return;
    int rows = min(TILE_M, ne - start);

    if (threadIdx.x < TILE_M) {
        int m = threadIdx.x;
        if (m < rows) {
            int pk = g_etok[e * T_TOKENS + start + m];
            toks[m]  = pk >> 2;
            slots[m] = pk & 3;
            wts[m]   = g_ewt[e * T_TOKENS + start + m];
        } else {
            toks[m] = 0; slots[m] = 0; wts[m] = 0.f;
        }
    }

    int tx = threadIdx.x & 15;   // n-dim, 8 cols each
    int ty = threadIdx.x >> 4;   // m-dim, 4 rows each

    const float* wgE = wg + (size_t)e * HDIM * IDIM;
    const float* wuE = wu + (size_t)e * HDIM * IDIM;
    const float* wdE = wd + (size_t)e * IDIM * HDIM;

    // ---------------- Phase A: h[64,512] = silu(x Wg) * (x Wu) ----------------
    for (int nb = 0; nb < IDIM / 128; ++nb) {
        float accg[8][4];
        float accu[8][4];
        #pragma unroll
        for (int j = 0; j < 8; ++j)
            #pragma unroll
            for (int i = 0; i < 4; ++i) { accg[j][i] = 0.f; accu[j][i] = 0.f; }

        for (int k0 = 0; k0 < HDIM; k0 += 32) {
            __syncthreads();
            // stage x tile transposed: xs[kk][m]
            for (int p = threadIdx.x; p < TILE_M * 8; p += 256) {
                int m = p >> 3, v = p & 7;
                float4 f = make_float4(0.f, 0.f, 0.f, 0.f);
                if (m < rows)
                    f = *(const float4*)(x + (size_t)toks[m] * HDIM + k0 + v * 4);
                xs[(v * 4 + 0) * XS_LD + m] = f.x;
                xs[(v * 4 + 1) * XS_LD + m] = f.y;
                xs[(v * 4 + 2) * XS_LD + m] = f.z;
                xs[(v * 4 + 3) * XS_LD + m] = f.w;
            }
            // stage Wg/Wu chunks: ws[kk][n]
            for (int q = threadIdx.x; q < 2048; q += 256) {
                int sel = q >> 10, r = q & 1023;
                int kk = r >> 5, n4 = r & 31;
                const float* src = (sel ? wuE : wgE) +
                                   (size_t)(k0 + kk) * IDIM + nb * 128 + n4 * 4;
                float4 f = *(const float4*)src;
                float* dst = (sel ? ws1 : ws0) + kk * 128 + n4 * 4;
                *(float4*)dst = f;
            }
            __syncthreads();

            #pragma unroll 4
            for (int kk = 0; kk < 32; ++kk) {
                float4 a  = *(float4*)(xs  + kk * XS_LD + ty * 4);
                float4 g0 = *(float4*)(ws0 + kk * 128 + tx * 8);
                float4 g1 = *(float4*)(ws0 + kk * 128 + tx * 8 + 4);
                float4 u0 = *(float4*)(ws1 + kk * 128 + tx * 8);
                float4 u1 = *(float4*)(ws1 + kk * 128 + tx * 8 + 4);
                float av[4] = {a.x, a.y, a.z, a.w};
                float gv[8] = {g0.x, g0.y, g0.z, g0.w, g1.x, g1.y, g1.z, g1.w};
                float uv[8] = {u0.x, u0.y, u0.z, u0.w, u1.x, u1.y, u1.z, u1.w};
                #pragma unroll
                for (int j = 0; j < 8; ++j)
                    #pragma unroll
                    for (int i = 0; i < 4; ++i) {
                        accg[j][i] += av[i] * gv[j];
                        accu[j][i] += av[i] * uv[j];
                    }
            }
        }
        // SwiGLU epilogue -> hs[n][m] (I-major so Phase B a-loads are LDS.128)
        #pragma unroll
        for (int j = 0; j < 8; ++j) {
            float h[4];
            #pragma unroll
            for (int i = 0; i < 4; ++i) {
                float g = accg[j][i];
                float s = 1.f / (1.f + __expf(-g));
                h[i] = accu[j][i] * g * s;
            }
            int n = nb * 128 + tx * 8 + j;
            *(float4*)(hs + (size_t)n * HS_LD + ty * 4) =
                make_float4(h[0], h[1], h[2], h[3]);
        }
    }

    // ---------------- Phase B: y[64,1024] = h Wd (weighted, to scratch) -------
    for (int nb = 0; nb < HDIM / 128; ++nb) {
        float acc[4][8];
        #pragma unroll
        for (int i = 0; i < 4; ++i)
            #pragma unroll
            for (int j = 0; j < 8; ++j) acc[i][j] = 0.f;

        for (int k0 = 0; k0 < IDIM; k0 += 32) {
            __syncthreads();
            for (int q = threadIdx.x; q < 1024; q += 256) {
                int kk = q >> 5, n4 = q & 31;
                float4 f = *(const float4*)(wdE + (size_t)(k0 + kk) * HDIM +
                                            nb * 128 + n4 * 4);
                *(float4*)(ws0 + kk * 128 + n4 * 4) = f;
            }
            __syncthreads();

            #pragma unroll 4
            for (int kk = 0; kk < 32; ++kk) {
                float4 a  = *(float4*)(hs + (size_t)(k0 + kk) * HS_LD + ty * 4);
                float4 b0 = *(float4*)(ws0 + kk * 128 + tx * 8);
                float4 b1 = *(float4*)(ws0 + kk * 128 + tx * 8 + 4);
                float av[4] = {a.x, a.y, a.z, a.w};
                float bv[8] = {b0.x, b0.y, b0.z, b0.w, b1.x, b1.y, b1.z, b1.w};
                #pragma unroll
                for (int i = 0; i < 4; ++i)
                    #pragma unroll
                    for (int j = 0; j < 8; ++j)
                        acc[i][j] += av[i] * bv[j];
            }
        }
        // weighted write to per-(token,slot) scratch
        #pragma unroll
        for (int i = 0; i < 4; ++i) {
            int m = ty * 4 + i;
            if (m < rows) {
                float w = wts[m];
                size_t base = ((size_t)toks[m] * TOPK + slots[m]) * HDIM +
                              nb * 128 + tx * 8;
                *(float4*)(g_scratch + base) =
                    make_float4(w * acc[i][0], w * acc[i][1],
                                w * acc[i][2], w * acc[i][3]);
                *(float4*)(g_scratch + base + 4) =
                    make_float4(w * acc[i][4], w * acc[i][5],
                                w * acc[i][6], w * acc[i][7]);
            }
        }
    }
}

// ---------------- combine: out[t][h] = sum_k scratch[t][k][h] -------------
__global__ void combine_kernel(float* __restrict__ out) {
    size_t i = (size_t)blockIdx.x * blockDim.x + threadIdx.x;  // float4 index
    const float4* s = (const float4*)g_scratch;
    size_t t = i >> 8;       // 256 float4 per row
    size_t c = i & 255;
    size_t base = t * (TOPK * 256) + c;
    float4 a = s[base], b = s[base + 256], cc = s[base + 512], d = s[base + 768];
    float4 o = make_float4(a.x + b.x + cc.x + d.x,
                           a.y + b.y + cc.y + d.y,
                           a.z + b.z + cc.z + d.z,
                           a.w + b.w + cc.w + d.w);
    ((float4*)out)[i] = o;
}

// ---------------- launch ---------------------------------------------------
extern "C" void kernel_launch(void* const* d_in, const int* in_sizes, int n_in,
                              void* d_out, int out_size) {
    const float* x  = (const float*)d_in[0];
    const float* gw = (const float*)d_in[1];
    const float* wg = (const float*)d_in[2];
    const float* wu = (const float*)d_in[3];
    const float* wd = (const float*)d_in[4];
    float* out = (float*)d_out;

    router_kernel<<<T_TOKENS / 8, 256>>>(x, gw);
    zero_cnt_kernel<<<1, 32>>>();
    scatter_kernel<<<T_TOKENS / 256, 256>>>();

    size_t smem = (size_t)(IDIM * HS_LD + 32 * XS_LD + 2 * 32 * 128) * sizeof(float);
    cudaFuncSetAttribute(expert_kernel,
                         cudaFuncAttributeMaxDynamicSharedMemorySize, (int)smem);
    dim3 grid(T_TOKENS / TILE_M, NEXP);
    expert_kernel<<<grid, 256, smem>>>(x, wg, wu, wd);

    combine_kernel<<<(T_TOKENS * HDIM / 4) / 256, 256>>>(out);
}

// round 4
// speedup vs baseline: 3.6332x; 3.6332x over previous
#include <cuda_runtime.h>
#include <math.h>
#include <stdint.h>

#define T_TOKENS 8192
#define HDIM 1024
#define IDIM 512
#define NEXP 32
#define TOPK 4
#define TILE_M 128
#define KC 32
#define XS_STR 36
#define WS_STR 37
#define BUFS 37376            // per double-buffer stage: max(PhaseA, PhaseB) bytes
#define WG_OFF 18432          // Phase A: xs[128][36] then wsg[64][37], wsu[64][37]
#define WU_OFF 27904
#define WD_OFF 18432          // Phase B: hs[128][36] then wsd[128][37]

// ---------------- device scratch ----------------
__device__ float g_partial[(size_t)T_TOKENS * TOPK * HDIM];   // 128 MB
__device__ float g_h[(size_t)T_TOKENS * TOPK * IDIM];         // 64 MB
__device__ int   g_top_idx[T_TOKENS * TOPK];
__device__ float g_top_wt [T_TOKENS * TOPK];
__device__ int   g_cnt[NEXP];
__device__ int   g_off[NEXP];
__device__ int   g_etok[NEXP * T_TOKENS];
__device__ float g_ewt [NEXP * T_TOKENS];

// ---------------- helpers ----------------
__device__ __forceinline__ float f2tf32(float x) {
    uint32_t o;
    asm("cvt.rna.tf32.f32 %0, %1;" : "=r"(o) : "f"(x));
    return __uint_as_float(o);
}
__device__ __forceinline__ float4 r4(float4 f) {
    f.x = f2tf32(f.x); f.y = f2tf32(f.y);
    f.z = f2tf32(f.z); f.w = f2tf32(f.w);
    return f;
}
#define MMA(d, a, b)                                                          \
    asm volatile(                                                             \
        "mma.sync.aligned.m16n8k8.row.col.f32.tf32.tf32.f32 "                 \
        "{%0,%1,%2,%3}, {%4,%5,%6,%7}, {%8,%9}, {%0,%1,%2,%3};"               \
        : "+f"((d)[0]), "+f"((d)[1]), "+f"((d)[2]), "+f"((d)[3])              \
        : "r"((a)[0]), "r"((a)[1]), "r"((a)[2]), "r"((a)[3]),                 \
          "r"((b)[0]), "r"((b)[1]))

// ---------------- router: logits -> top-4 ----------------
__global__ void router_kernel(const float* __restrict__ x,
                              const float* __restrict__ gw) {
    __shared__ float xs[8][HDIM];
    int t0 = blockIdx.x * 8;
    for (int i = threadIdx.x; i < 8 * (HDIM / 4); i += blockDim.x) {
        int row = i >> 8;
        int c4  = i & 255;
        ((float4*)xs[row])[c4] = ((const float4*)(x + (size_t)(t0 + row) * HDIM))[c4];
    }
    __syncthreads();

    int w = threadIdx.x >> 5;
    int lane = threadIdx.x & 31;
    int t = t0 + w;
    const float* xr = xs[w];

    float myLogit = 0.f;
    for (int e = 0; e < NEXP; ++e) {
        const float* wr = gw + (size_t)e * HDIM;
        float s = 0.f;
        #pragma unroll 8
        for (int j = lane; j < HDIM; j += 32) s += xr[j] * wr[j];
        #pragma unroll
        for (int off = 16; off; off >>= 1) s += __shfl_xor_sync(0xffffffffu, s, off);
        if (lane == e) myLogit = s;
    }

    float v = myLogit;
    float selv[TOPK];
    int   seli[TOPK];
    #pragma unroll
    for (int k = 0; k < TOPK; ++k) {
        float bv = v; int bi = lane;
        #pragma unroll
        for (int off = 16; off; off >>= 1) {
            float ov = __shfl_xor_sync(0xffffffffu, bv, off);
            int   oi = __shfl_xor_sync(0xffffffffu, bi, off);
            if (ov > bv || (ov == bv && oi < bi)) { bv = ov; bi = oi; }
        }
        selv[k] = bv; seli[k] = bi;
        if (lane == bi) v = -1e30f;
    }

    if (lane == 0) {
        float m = selv[0];
        float ew[TOPK];
        float sum = 0.f;
        #pragma unroll
        for (int k = 0; k < TOPK; ++k) { ew[k] = expf(selv[k] - m); sum += ew[k]; }
        float inv = 1.f / sum;
        #pragma unroll
        for (int k = 0; k < TOPK; ++k) {
            g_top_idx[t * TOPK + k] = seli[k];
            g_top_wt [t * TOPK + k] = ew[k] * inv;
        }
    }
}

__global__ void zero_cnt_kernel() {
    if (threadIdx.x < NEXP) g_cnt[threadIdx.x] = 0;
}

__global__ void scatter_kernel() {
    int t = blockIdx.x * blockDim.x + threadIdx.x;
    if (t >= T_TOKENS) return;
    #pragma unroll
    for (int k = 0; k < TOPK; ++k) {
        int e = g_top_idx[t * TOPK + k];
        int pos = atomicAdd(&g_cnt[e], 1);
        g_etok[e * T_TOKENS + pos] = (t << 2) | k;
        g_ewt [e * T_TOKENS + pos] = g_top_wt[t * TOPK + k];
    }
}

__global__ void prefix_kernel() {
    if (threadIdx.x == 0) {
        int a = 0;
        for (int e = 0; e < NEXP; ++e) { g_off[e] = a; a += g_cnt[e]; }
    }
}

// ---------------- expert: tf32 mma.sync ----------------
__global__ void __launch_bounds__(256, 1)
expert_mma(const float* __restrict__ x, const float* __restrict__ wg,
           const float* __restrict__ wu, const float* __restrict__ wd) {
    extern __shared__ char sm[];
    __shared__ int   s_tok[TILE_M];
    __shared__ int   s_slot[TILE_M];
    __shared__ float s_wt[TILE_M];

    int e = blockIdx.y;
    int cnt = g_cnt[e];
    int start = blockIdx.x * TILE_M;
    if (start >= cnt) return;
    int rows = min(TILE_M, cnt - start);

    int tid = threadIdx.x;
    int wid = tid >> 5, lane = tid & 31;
    int r = lane >> 2, tig = lane & 3;
    int m0 = (wid & 3) * 32;
    int n0a = (wid >> 2) * 32;   // Phase A warp N-offset (of 64)
    int n0b = (wid >> 2) * 64;   // Phase B warp N-offset (of 128)

    if (tid < TILE_M) {
        if (tid < rows) {
            int pk = g_etok[e * T_TOKENS + start + tid];
            s_tok[tid] = pk >> 2; s_slot[tid] = pk & 3;
            s_wt[tid] = g_ewt[e * T_TOKENS + start + tid];
        } else { s_tok[tid] = 0; s_slot[tid] = 0; s_wt[tid] = 0.f; }
    }
    __syncthreads();

    const float* wgE = wg + (size_t)e * HDIM * IDIM;
    const float* wuE = wu + (size_t)e * HDIM * IDIM;
    const float* wdE = wd + (size_t)e * IDIM * HDIM;
    int hbase = g_off[e] + start;

    // ==================== Phase A: h = silu(x Wg) * (x Wu) ====================
    for (int nb = 0; nb < IDIM / 64; ++nb) {
        float accg[2][4][4], accu[2][4][4];
        #pragma unroll
        for (int i = 0; i < 2; ++i)
            #pragma unroll
            for (int j = 0; j < 4; ++j)
                #pragma unroll
                for (int c4 = 0; c4 < 4; ++c4) { accg[i][j][c4] = 0.f; accu[i][j][c4] = 0.f; }

        // prologue: stage chunk 0 into buffer 0
        {
            float* xsb = (float*)(sm);
            float* wgb = (float*)(sm + WG_OFF);
            float* wub = (float*)(sm + WU_OFF);
            #pragma unroll
            for (int i2 = 0; i2 < 4; ++i2) {
                int idx = tid + i2 * 256;
                int m = idx >> 3, kq = idx & 7;
                float4 f = make_float4(0.f, 0.f, 0.f, 0.f);
                if (m < rows)
                    f = r4(*(const float4*)(x + (size_t)s_tok[m] * HDIM + kq * 4));
                *(float4*)(xsb + m * XS_STR + kq * 4) = f;
            }
            #pragma unroll
            for (int i2 = 0; i2 < 2; ++i2) {
                int idx = tid + i2 * 256;
                int k = idx >> 4, nq = idx & 15;
                float4 fg = r4(*(const float4*)(wgE + (size_t)k * IDIM + nb * 64 + nq * 4));
                float4 fu = r4(*(const float4*)(wuE + (size_t)k * IDIM + nb * 64 + nq * 4));
                #pragma unroll
                for (int t4 = 0; t4 < 4; ++t4) {
                    wgb[(nq * 4 + t4) * WS_STR + k] = (&fg.x)[t4];
                    wub[(nq * 4 + t4) * WS_STR + k] = (&fu.x)[t4];
                }
            }
        }
        __syncthreads();

        for (int c = 0; c < HDIM / KC; ++c) {
            // prefetch next chunk into regs
            float4 rx[4], rg[2], ru[2];
            int nk = HDIM / KC;
            if (c + 1 < nk) {
                int k0 = (c + 1) * KC;
                #pragma unroll
                for (int i2 = 0; i2 < 4; ++i2) {
                    int idx = tid + i2 * 256;
                    int m = idx >> 3, kq = idx & 7;
                    float4 f = make_float4(0.f, 0.f, 0.f, 0.f);
                    if (m < rows)
                        f = *(const float4*)(x + (size_t)s_tok[m] * HDIM + k0 + kq * 4);
                    rx[i2] = r4(f);
                }
                #pragma unroll
                for (int i2 = 0; i2 < 2; ++i2) {
                    int idx = tid + i2 * 256;
                    int k = idx >> 4, nq = idx & 15;
                    rg[i2] = r4(*(const float4*)(wgE + (size_t)(k0 + k) * IDIM + nb * 64 + nq * 4));
                    ru[i2] = r4(*(const float4*)(wuE + (size_t)(k0 + k) * IDIM + nb * 64 + nq * 4));
                }
            }
            // compute current chunk
            {
                const uint32_t* xsu = (const uint32_t*)(sm + (c & 1) * BUFS);
                const uint32_t* wgu = (const uint32_t*)(sm + (c & 1) * BUFS + WG_OFF);
                const uint32_t* wuu = (const uint32_t*)(sm + (c & 1) * BUFS + WU_OFF);
                #pragma unroll
                for (int ks = 0; ks < 4; ++ks) {
                    uint32_t a[2][4];
                    #pragma unroll
                    for (int i = 0; i < 2; ++i) {
                        const uint32_t* p = xsu + (m0 + 16 * i + r) * XS_STR + ks * 8 + tig;
                        a[i][0] = p[0];
                        a[i][1] = p[8 * XS_STR];
                        a[i][2] = p[4];
                        a[i][3] = p[8 * XS_STR + 4];
                    }
                    #pragma unroll
                    for (int j = 0; j < 4; ++j) {
                        uint32_t bg[2], bu[2];
                        const uint32_t* qg = wgu + (n0a + 8 * j + r) * WS_STR + ks * 8 + tig;
                        const uint32_t* qu = wuu + (n0a + 8 * j + r) * WS_STR + ks * 8 + tig;
                        bg[0] = qg[0]; bg[1] = qg[4];
                        bu[0] = qu[0]; bu[1] = qu[4];
                        MMA(accg[0][j], a[0], bg);
                        MMA(accg[1][j], a[1], bg);
                        MMA(accu[0][j], a[0], bu);
                        MMA(accu[1][j], a[1], bu);
                    }
                }
            }
            // store prefetched chunk into alternate buffer
            if (c + 1 < nk) {
                char* bufp = sm + ((c + 1) & 1) * BUFS;
                float* xsb = (float*)(bufp);
                float* wgb = (float*)(bufp + WG_OFF);
                float* wub = (float*)(bufp + WU_OFF);
                #pragma unroll
                for (int i2 = 0; i2 < 4; ++i2) {
                    int idx = tid + i2 * 256;
                    int m = idx >> 3, kq = idx & 7;
                    *(float4*)(xsb + m * XS_STR + kq * 4) = rx[i2];
                }
                #pragma unroll
                for (int i2 = 0; i2 < 2; ++i2) {
                    int idx = tid + i2 * 256;
                    int k = idx >> 4, nq = idx & 15;
                    #pragma unroll
                    for (int t4 = 0; t4 < 4; ++t4) {
                        wgb[(nq * 4 + t4) * WS_STR + k] = (&rg[i2].x)[t4];
                        wub[(nq * 4 + t4) * WS_STR + k] = (&ru[i2].x)[t4];
                    }
                }
            }
            __syncthreads();
        }

        // epilogue: silu(gate)*up -> g_h
        #pragma unroll
        for (int i = 0; i < 2; ++i) {
            #pragma unroll
            for (int half = 0; half < 2; ++half) {
                int m = m0 + 16 * i + r + 8 * half;
                if (m < rows) {
                    float* hp = g_h + (size_t)(hbase + m) * IDIM + nb * 64 + n0a;
                    #pragma unroll
                    for (int j = 0; j < 4; ++j) {
                        float g0 = accg[i][j][half * 2 + 0];
                        float g1 = accg[i][j][half * 2 + 1];
                        float u0 = accu[i][j][half * 2 + 0];
                        float u1 = accu[i][j][half * 2 + 1];
                        float h0 = f2tf32(u0 * g0 / (1.f + __expf(-g0)));
                        float h1 = f2tf32(u1 * g1 / (1.f + __expf(-g1)));
                        *(float2*)(hp + 8 * j + 2 * tig) = make_float2(h0, h1);
                    }
                }
            }
        }
        __syncthreads();
    }

    // ==================== Phase B: y = (h Wd) * route_w ====================
    for (int nb = 0; nb < HDIM / 128; ++nb) {
        float acc[2][8][4];
        #pragma unroll
        for (int i = 0; i < 2; ++i)
            #pragma unroll
            for (int j = 0; j < 8; ++j)
                #pragma unroll
                for (int c4 = 0; c4 < 4; ++c4) acc[i][j][c4] = 0.f;

        // prologue: stage chunk 0
        {
            float* hsb = (float*)(sm);
            float* wdb = (float*)(sm + WD_OFF);
            #pragma unroll
            for (int i2 = 0; i2 < 4; ++i2) {
                int idx = tid + i2 * 256;
                int m = idx >> 3, kq = idx & 7;
                float4 f = make_float4(0.f, 0.f, 0.f, 0.f);
                if (m < rows)
                    f = *(const float4*)(g_h + (size_t)(hbase + m) * IDIM + kq * 4);
                *(float4*)(hsb + m * XS_STR + kq * 4) = f;
            }
            #pragma unroll
            for (int i2 = 0; i2 < 4; ++i2) {
                int idx = tid + i2 * 256;
                int k = idx >> 5, nq = idx & 31;
                float4 f = r4(*(const float4*)(wdE + (size_t)k * HDIM + nb * 128 + nq * 4));
                #pragma unroll
                for (int t4 = 0; t4 < 4; ++t4)
                    wdb[(nq * 4 + t4) * WS_STR + k] = (&f.x)[t4];
            }
        }
        __syncthreads();

        for (int c = 0; c < IDIM / KC; ++c) {
            float4 rh[4], rw[4];
            int nk = IDIM / KC;
            if (c + 1 < nk) {
                int k0 = (c + 1) * KC;
                #pragma unroll
                for (int i2 = 0; i2 < 4; ++i2) {
                    int idx = tid + i2 * 256;
                    int m = idx >> 3, kq = idx & 7;
                    float4 f = make_float4(0.f, 0.f, 0.f, 0.f);
                    if (m < rows)
                        f = *(const float4*)(g_h + (size_t)(hbase + m) * IDIM + k0 + kq * 4);
                    rh[i2] = f;
                }
                #pragma unroll
                for (int i2 = 0; i2 < 4; ++i2) {
                    int idx = tid + i2 * 256;
                    int k = idx >> 5, nq = idx & 31;
                    rw[i2] = r4(*(const float4*)(wdE + (size_t)(k0 + k) * HDIM + nb * 128 + nq * 4));
                }
            }
            {
                const uint32_t* hsu = (const uint32_t*)(sm + (c & 1) * BUFS);
                const uint32_t* wdu = (const uint32_t*)(sm + (c & 1) * BUFS + WD_OFF);
                #pragma unroll
                for (int ks = 0; ks < 4; ++ks) {
                    uint32_t a[2][4];
                    #pragma unroll
                    for (int i = 0; i < 2; ++i) {
                        const uint32_t* p = hsu + (m0 + 16 * i + r) * XS_STR + ks * 8 + tig;
                        a[i][0] = p[0];
                        a[i][1] = p[8 * XS_STR];
                        a[i][2] = p[4];
                        a[i][3] = p[8 * XS_STR + 4];
                    }
                    #pragma unroll
                    for (int j = 0; j < 8; ++j) {
                        uint32_t b[2];
                        const uint32_t* q = wdu + (n0b + 8 * j + r) * WS_STR + ks * 8 + tig;
                        b[0] = q[0]; b[1] = q[4];
                        MMA(acc[0][j], a[0], b);
                        MMA(acc[1][j], a[1], b);
                    }
                }
            }
            if (c + 1 < nk) {
                char* bufp = sm + ((c + 1) & 1) * BUFS;
                float* hsb = (float*)(bufp);
                float* wdb = (float*)(bufp + WD_OFF);
                #pragma unroll
                for (int i2 = 0; i2 < 4; ++i2) {
                    int idx = tid + i2 * 256;
                    int m = idx >> 3, kq = idx & 7;
                    *(float4*)(hsb + m * XS_STR + kq * 4) = rh[i2];
                }
                #pragma unroll
                for (int i2 = 0; i2 < 4; ++i2) {
                    int idx = tid + i2 * 256;
                    int k = idx >> 5, nq = idx & 31;
                    #pragma unroll
                    for (int t4 = 0; t4 < 4; ++t4)
                        wdb[(nq * 4 + t4) * WS_STR + k] = (&rw[i2].x)[t4];
                }
            }
            __syncthreads();
        }

        // epilogue: apply routing weight, write partials
        #pragma unroll
        for (int i = 0; i < 2; ++i) {
            #pragma unroll
            for (int half = 0; half < 2; ++half) {
                int m = m0 + 16 * i + r + 8 * half;
                if (m < rows) {
                    float wgt = s_wt[m];
                    float* dp = g_partial +
                        ((size_t)s_tok[m] * TOPK + s_slot[m]) * HDIM + nb * 128 + n0b;
                    #pragma unroll
                    for (int j = 0; j < 8; ++j) {
                        float y0 = wgt * acc[i][j][half * 2 + 0];
                        float y1 = wgt * acc[i][j][half * 2 + 1];
                        *(float2*)(dp + 8 * j + 2 * tig) = make_float2(y0, y1);
                    }
                }
            }
        }
        __syncthreads();
    }
}

// ---------------- combine: out[t][h] = sum_k partial[t][k][h] ----------------
__global__ void combine_kernel(float* __restrict__ out) {
    size_t i = (size_t)blockIdx.x * blockDim.x + threadIdx.x;
    const float4* s = (const float4*)g_partial;
    size_t t = i >> 8;
    size_t c = i & 255;
    size_t base = t * (TOPK * 256) + c;
    float4 a = s[base], b = s[base + 256], cc = s[base + 512], d = s[base + 768];
    ((float4*)out)[i] = make_float4(a.x + b.x + cc.x + d.x,
                                    a.y + b.y + cc.y + d.y,
                                    a.z + b.z + cc.z + d.z,
                                    a.w + b.w + cc.w + d.w);
}

// ---------------- launch ----------------
extern "C" void kernel_launch(void* const* d_in, const int* in_sizes, int n_in,
                              void* d_out, int out_size) {
    const float* x  = (const float*)d_in[0];
    const float* gw = (const float*)d_in[1];
    const float* wg = (const float*)d_in[2];
    const float* wu = (const float*)d_in[3];
    const float* wd = (const float*)d_in[4];
    float* out = (float*)d_out;

    router_kernel<<<T_TOKENS / 8, 256>>>(x, gw);
    zero_cnt_kernel<<<1, 32>>>();
    scatter_kernel<<<T_TOKENS / 256, 256>>>();
    prefix_kernel<<<1, 32>>>();

    int smem = 2 * BUFS;
    cudaFuncSetAttribute(expert_mma,
                         cudaFuncAttributeMaxDynamicSharedMemorySize, smem);
    dim3 grid(T_TOKENS / TILE_M, NEXP);
    expert_mma<<<grid, 256, smem>>>(x, wg, wu, wd);

    combine_kernel<<<(T_TOKENS * HDIM / 4) / 256, 256>>>(out);
}

// round 5
// speedup vs baseline: 5.9015x; 1.6243x over previous
#include <cuda_runtime.h>
#include <math.h>
#include <stdint.h>

#define T_TOKENS 8192
#define HDIM 1024
#define IDIM 512
#define NEXP 32
#define TOPK 4
#define TILE_M 128
#define KC 32
#define STR 36                 // smem row stride in floats (bank-conflict pad)
#define STAGE 36864            // bytes per pipeline stage
#define WG_OFF 18432
#define WU_OFF 27648
#define WD_OFF 18432

// ---------------- device scratch ----------------
__device__ float g_partial[(size_t)T_TOKENS * TOPK * HDIM];   // 128 MB
__device__ float g_h[(size_t)T_TOKENS * TOPK * IDIM];         // 64 MB
__device__ float g_xr[(size_t)T_TOKENS * HDIM];               // 32 MB rounded x
__device__ float g_wgt[(size_t)NEXP * IDIM * HDIM];           // 64 MB [E][I][H]
__device__ float g_wut[(size_t)NEXP * IDIM * HDIM];           // 64 MB [E][I][H]
__device__ float g_wdt[(size_t)NEXP * HDIM * IDIM];           // 64 MB [E][H][I]
__device__ int   g_top_idx[T_TOKENS * TOPK];
__device__ float g_top_wt [T_TOKENS * TOPK];
__device__ int   g_cnt[NEXP];
__device__ int   g_off[NEXP];
__device__ int   g_etok[NEXP * T_TOKENS];
__device__ float g_ewt [NEXP * T_TOKENS];
__device__ int   g_tiles[2048];
__device__ int   g_ntiles;
__device__ int   g_ticket;

// ---------------- helpers ----------------
__device__ __forceinline__ uint32_t smem_u32(const void* p) {
    uint32_t a;
    asm("{ .reg .u64 t; cvta.to.shared.u64 t, %1; cvt.u32.u64 %0, t; }"
        : "=r"(a) : "l"(p));
    return a;
}
__device__ __forceinline__ float f2tf32(float x) {
    uint32_t o;
    asm("cvt.rna.tf32.f32 %0, %1;" : "=r"(o) : "f"(x));
    return __uint_as_float(o);
}
__device__ __forceinline__ void cpa16(uint32_t dst, const float* src, int sz) {
    asm volatile("cp.async.ca.shared.global [%0], [%1], 16, %2;"
                 :: "r"(dst), "l"(src), "r"(sz) : "memory");
}
#define CP_COMMIT() asm volatile("cp.async.commit_group;" ::: "memory")
#define CP_WAIT(n)  asm volatile("cp.async.wait_group %0;" :: "n"(n) : "memory")
#define MMA(d, a, b)                                                          \
    asm volatile(                                                             \
        "mma.sync.aligned.m16n8k8.row.col.f32.tf32.tf32.f32 "                 \
        "{%0,%1,%2,%3}, {%4,%5,%6,%7}, {%8,%9}, {%0,%1,%2,%3};"               \
        : "+f"((d)[0]), "+f"((d)[1]), "+f"((d)[2]), "+f"((d)[3])              \
        : "r"((a)[0]), "r"((a)[1]), "r"((a)[2]), "r"((a)[3]),                 \
          "r"((b)[0]), "r"((b)[1]))

// ---------------- preprocessing ----------------
__global__ void round_x_kernel(const float* __restrict__ x) {
    size_t i = (size_t)blockIdx.x * blockDim.x + threadIdx.x;
    float4 f = ((const float4*)x)[i];
    f.x = f2tf32(f.x); f.y = f2tf32(f.y);
    f.z = f2tf32(f.z); f.w = f2tf32(f.w);
    ((float4*)g_xr)[i] = f;
}

// round + transpose weights: z=0 wg->[I][H], z=1 wu->[I][H], z=2 wd->[H][I]
__global__ void transpose_kernel(const float* __restrict__ wg,
                                 const float* __restrict__ wu,
                                 const float* __restrict__ wd) {
    __shared__ float t[32][33];
    int sel = blockIdx.z;
    int e = blockIdx.y;
    int R = (sel == 2) ? IDIM : HDIM;
    int C = (sel == 2) ? HDIM : IDIM;
    int tilesC = C >> 5;
    int r0 = (blockIdx.x / tilesC) << 5;
    int c0 = (blockIdx.x % tilesC) << 5;
    const float* src = ((sel == 0) ? wg : (sel == 1) ? wu : wd) +
                       (size_t)e * HDIM * IDIM;
    float* dst = ((sel == 0) ? g_wgt : (sel == 1) ? g_wut : g_wdt) +
                 (size_t)e * HDIM * IDIM;
    int tx = threadIdx.x & 31, ty = threadIdx.x >> 5;
    #pragma unroll
    for (int i = 0; i < 4; ++i)
        t[ty + 8 * i][tx] = f2tf32(src[(size_t)(r0 + ty + 8 * i) * C + c0 + tx]);
    __syncthreads();
    #pragma unroll
    for (int i = 0; i < 4; ++i)
        dst[(size_t)(c0 + ty + 8 * i) * R + r0 + tx] = t[tx][ty + 8 * i];
}

// ---------------- router: logits -> top-4 ----------------
__global__ void router_kernel(const float* __restrict__ x,
                              const float* __restrict__ gw) {
    __shared__ float xs[8][HDIM];
    int t0 = blockIdx.x * 8;
    for (int i = threadIdx.x; i < 8 * (HDIM / 4); i += blockDim.x) {
        int row = i >> 8;
        int c4  = i & 255;
        ((float4*)xs[row])[c4] = ((const float4*)(x + (size_t)(t0 + row) * HDIM))[c4];
    }
    __syncthreads();

    int w = threadIdx.x >> 5;
    int lane = threadIdx.x & 31;
    int t = t0 + w;
    const float* xr = xs[w];

    float myLogit = 0.f;
    for (int e = 0; e < NEXP; ++e) {
        const float* wr = gw + (size_t)e * HDIM;
        float s = 0.f;
        #pragma unroll 8
        for (int j = lane; j < HDIM; j += 32) s += xr[j] * wr[j];
        #pragma unroll
        for (int off = 16; off; off >>= 1) s += __shfl_xor_sync(0xffffffffu, s, off);
        if (lane == e) myLogit = s;
    }

    float v = myLogit;
    float selv[TOPK];
    int   seli[TOPK];
    #pragma unroll
    for (int k = 0; k < TOPK; ++k) {
        float bv = v; int bi = lane;
        #pragma unroll
        for (int off = 16; off; off >>= 1) {
            float ov = __shfl_xor_sync(0xffffffffu, bv, off);
            int   oi = __shfl_xor_sync(0xffffffffu, bi, off);
            if (ov > bv || (ov == bv && oi < bi)) { bv = ov; bi = oi; }
        }
        selv[k] = bv; seli[k] = bi;
        if (lane == bi) v = -1e30f;
    }

    if (lane == 0) {
        float m = selv[0];
        float ew[TOPK];
        float sum = 0.f;
        #pragma unroll
        for (int k = 0; k < TOPK; ++k) { ew[k] = expf(selv[k] - m); sum += ew[k]; }
        float inv = 1.f / sum;
        #pragma unroll
        for (int k = 0; k < TOPK; ++k) {
            g_top_idx[t * TOPK + k] = seli[k];
            g_top_wt [t * TOPK + k] = ew[k] * inv;
        }
    }
}

__global__ void zero_cnt_kernel() {
    if (threadIdx.x < NEXP) g_cnt[threadIdx.x] = 0;
}

__global__ void scatter_kernel() {
    int t = blockIdx.x * blockDim.x + threadIdx.x;
    if (t >= T_TOKENS) return;
    #pragma unroll
    for (int k = 0; k < TOPK; ++k) {
        int e = g_top_idx[t * TOPK + k];
        int pos = atomicAdd(&g_cnt[e], 1);
        g_etok[e * T_TOKENS + pos] = (t << 2) | k;
        g_ewt [e * T_TOKENS + pos] = g_top_wt[t * TOPK + k];
    }
}

__global__ void prefix_kernel() {
    if (threadIdx.x == 0) {
        int a = 0, nt = 0;
        for (int e = 0; e < NEXP; ++e) {
            g_off[e] = a;
            int c = g_cnt[e];
            a += c;
            int nt_e = (c + TILE_M - 1) / TILE_M;
            for (int t = 0; t < nt_e; ++t) g_tiles[nt++] = (e << 16) | t;
        }
        g_ntiles = nt;
        g_ticket = 0;
    }
}

// ---------------- expert: tf32 mma.sync, cp.async pipeline -------------
__global__ void __launch_bounds__(256, 2)
expert_mma(const float* __restrict__ dummy) {
    extern __shared__ char sm[];
    __shared__ int   s_tok[TILE_M];
    __shared__ int   s_slot[TILE_M];
    __shared__ float s_wt[TILE_M];
    __shared__ int   s_tile;

    uint32_t smb = smem_u32(sm);
    int tid = threadIdx.x;
    int wid = tid >> 5, lane = tid & 31;
    int r = lane >> 2, tig = lane & 3;
    int m0 = (wid & 3) * 32;
    int gsel = wid >> 2;
    int n0a = gsel * 32;
    int n0b = gsel * 64;

    for (;;) {
        __syncthreads();
        if (tid == 0) s_tile = atomicAdd(&g_ticket, 1);
        __syncthreads();
        int tI = s_tile;
        if (tI >= g_ntiles) return;
        int pk_t = g_tiles[tI];
        int e = pk_t >> 16;
        int start = (pk_t & 0xffff) * TILE_M;
        int cnt = g_cnt[e];
        int rows = min(TILE_M, cnt - start);

        if (tid < TILE_M) {
            if (tid < rows) {
                int pk = g_etok[e * T_TOKENS + start + tid];
                s_tok[tid] = pk >> 2; s_slot[tid] = pk & 3;
                s_wt[tid] = g_ewt[e * T_TOKENS + start + tid];
            } else { s_tok[tid] = 0; s_slot[tid] = 0; s_wt[tid] = 0.f; }
        }
        __syncthreads();

        const float* wgtE = g_wgt + (size_t)e * HDIM * IDIM;
        const float* wutE = g_wut + (size_t)e * HDIM * IDIM;
        const float* wdtE = g_wdt + (size_t)e * HDIM * IDIM;
        int hbase = g_off[e] + start;

        // ============== Phase A: h = silu(x Wg) * (x Wu) ==============
        for (int nb = 0; nb < IDIM / 64; ++nb) {
            float accg[2][4][4], accu[2][4][4];
            #pragma unroll
            for (int i = 0; i < 2; ++i)
                #pragma unroll
                for (int j = 0; j < 4; ++j)
                    #pragma unroll
                    for (int q = 0; q < 4; ++q) { accg[i][j][q] = 0.f; accu[i][j][q] = 0.f; }

            // stage chunk c into buffer (c&1)
            #define STAGE_A(c)  do {                                               \
                uint32_t sb = smb + ((c) & 1) * STAGE;                             \
                int k0 = (c) * KC;                                                 \
                _Pragma("unroll")                                                  \
                for (int i2 = 0; i2 < 4; ++i2) {                                   \
                    int idx = tid + i2 * 256;                                      \
                    int m = idx >> 3, seg = idx & 7;                               \
                    cpa16(sb + m * 144 + seg * 16,                                 \
                          g_xr + (size_t)s_tok[m] * HDIM + k0 + seg * 4,           \
                          (m < rows) ? 16 : 0);                                    \
                }                                                                  \
                _Pragma("unroll")                                                  \
                for (int i2 = 0; i2 < 2; ++i2) {                                   \
                    int idx = tid + i2 * 256;                                      \
                    int n = idx >> 3, seg = idx & 7;                               \
                    const float* sg = wgtE + (size_t)(nb * 64 + n) * HDIM + k0 + seg * 4; \
                    const float* su = wutE + (size_t)(nb * 64 + n) * HDIM + k0 + seg * 4; \
                    cpa16(sb + WG_OFF + n * 144 + seg * 16, sg, 16);               \
                    cpa16(sb + WU_OFF + n * 144 + seg * 16, su, 16);               \
                }                                                                  \
                CP_COMMIT();                                                       \
            } while (0)

            STAGE_A(0);
            for (int c = 0; c < HDIM / KC; ++c) {
                if (c + 1 < HDIM / KC) { STAGE_A(c + 1); CP_WAIT(1); }
                else                   { CP_WAIT(0); }
                __syncthreads();
                const uint32_t* xsu = (const uint32_t*)(sm + (c & 1) * STAGE);
                const uint32_t* wgu = (const uint32_t*)(sm + (c & 1) * STAGE + WG_OFF);
                const uint32_t* wuu = (const uint32_t*)(sm + (c & 1) * STAGE + WU_OFF);
                #pragma unroll
                for (int ks = 0; ks < 4; ++ks) {
                    uint32_t a[2][4];
                    #pragma unroll
                    for (int i = 0; i < 2; ++i) {
                        const uint32_t* p = xsu + (m0 + 16 * i + r) * STR + ks * 8 + tig;
                        a[i][0] = p[0];
                        a[i][1] = p[8 * STR];
                        a[i][2] = p[4];
                        a[i][3] = p[8 * STR + 4];
                    }
                    #pragma unroll
                    for (int j = 0; j < 4; ++j) {
                        uint32_t bg[2], bu[2];
                        const uint32_t* qg = wgu + (n0a + 8 * j + r) * STR + ks * 8 + tig;
                        const uint32_t* qu = wuu + (n0a + 8 * j + r) * STR + ks * 8 + tig;
                        bg[0] = qg[0]; bg[1] = qg[4];
                        bu[0] = qu[0]; bu[1] = qu[4];
                        MMA(accg[0][j], a[0], bg);
                        MMA(accg[1][j], a[1], bg);
                        MMA(accu[0][j], a[0], bu);
                        MMA(accu[1][j], a[1], bu);
                    }
                }
                __syncthreads();
            }
            #undef STAGE_A

            // epilogue: silu(gate)*up -> g_h (tf32-rounded)
            #pragma unroll
            for (int i = 0; i < 2; ++i) {
                #pragma unroll
                for (int half = 0; half < 2; ++half) {
                    int m = m0 + 16 * i + r + 8 * half;
                    if (m < rows) {
                        float* hp = g_h + (size_t)(hbase + m) * IDIM + nb * 64 + n0a;
                        #pragma unroll
                        for (int j = 0; j < 4; ++j) {
                            float g0 = accg[i][j][half * 2 + 0];
                            float g1 = accg[i][j][half * 2 + 1];
                            float u0 = accu[i][j][half * 2 + 0];
                            float u1 = accu[i][j][half * 2 + 1];
                            float h0 = f2tf32(u0 * g0 / (1.f + __expf(-g0)));
                            float h1 = f2tf32(u1 * g1 / (1.f + __expf(-g1)));
                            *(float2*)(hp + 8 * j + 2 * tig) = make_float2(h0, h1);
                        }
                    }
                }
            }
            __syncthreads();
        }

        // ============== Phase B: y = (h Wd) * route_w ==============
        for (int nb = 0; nb < HDIM / 128; ++nb) {
            float acc[2][8][4];
            #pragma unroll
            for (int i = 0; i < 2; ++i)
                #pragma unroll
                for (int j = 0; j < 8; ++j)
                    #pragma unroll
                    for (int q = 0; q < 4; ++q) acc[i][j][q] = 0.f;

            #define STAGE_B(c)  do {                                               \
                uint32_t sb = smb + ((c) & 1) * STAGE;                             \
                int k0 = (c) * KC;                                                 \
                _Pragma("unroll")                                                  \
                for (int i2 = 0; i2 < 4; ++i2) {                                   \
                    int idx = tid + i2 * 256;                                      \
                    int m = idx >> 3, seg = idx & 7;                               \
                    cpa16(sb + m * 144 + seg * 16,                                 \
                          g_h + (size_t)(hbase + m) * IDIM + k0 + seg * 4,         \
                          (m < rows) ? 16 : 0);                                    \
                }                                                                  \
                _Pragma("unroll")                                                  \
                for (int i2 = 0; i2 < 4; ++i2) {                                   \
                    int idx = tid + i2 * 256;                                      \
                    int n = idx >> 3, seg = idx & 7;                               \
                    cpa16(sb + WD_OFF + n * 144 + seg * 16,                        \
                          wdtE + (size_t)(nb * 128 + n) * IDIM + k0 + seg * 4, 16);\
                }                                                                  \
                CP_COMMIT();                                                       \
            } while (0)

            STAGE_B(0);
            for (int c = 0; c < IDIM / KC; ++c) {
                if (c + 1 < IDIM / KC) { STAGE_B(c + 1); CP_WAIT(1); }
                else                   { CP_WAIT(0); }
                __syncthreads();
                const uint32_t* hsu = (const uint32_t*)(sm + (c & 1) * STAGE);
                const uint32_t* wdu = (const uint32_t*)(sm + (c & 1) * STAGE + WD_OFF);
                #pragma unroll
                for (int ks = 0; ks < 4; ++ks) {
                    uint32_t a[2][4];
                    #pragma unroll
                    for (int i = 0; i < 2; ++i) {
                        const uint32_t* p = hsu + (m0 + 16 * i + r) * STR + ks * 8 + tig;
                        a[i][0] = p[0];
                        a[i][1] = p[8 * STR];
                        a[i][2] = p[4];
                        a[i][3] = p[8 * STR + 4];
                    }
                    #pragma unroll
                    for (int j = 0; j < 8; ++j) {
                        uint32_t b[2];
                        const uint32_t* q = wdu + (n0b + 8 * j + r) * STR + ks * 8 + tig;
                        b[0] = q[0]; b[1] = q[4];
                        MMA(acc[0][j], a[0], b);
                        MMA(acc[1][j], a[1], b);
                    }
                }
                __syncthreads();
            }
            #undef STAGE_B

            // epilogue: apply routing weight, write partials
            #pragma unroll
            for (int i = 0; i < 2; ++i) {
                #pragma unroll
                for (int half = 0; half < 2; ++half) {
                    int m = m0 + 16 * i + r + 8 * half;
                    if (m < rows) {
                        float wgt = s_wt[m];
                        float* dp = g_partial +
                            ((size_t)s_tok[m] * TOPK + s_slot[m]) * HDIM + nb * 128 + n0b;
                        #pragma unroll
                        for (int j = 0; j < 8; ++j) {
                            float y0 = wgt * acc[i][j][half * 2 + 0];
                            float y1 = wgt * acc[i][j][half * 2 + 1];
                            *(float2*)(dp + 8 * j + 2 * tig) = make_float2(y0, y1);
                        }
                    }
                }
            }
            __syncthreads();
        }
    }
}

// ---------------- combine: out[t][h] = sum_k partial[t][k][h] -------------
__global__ void combine_kernel(float* __restrict__ out) {
    size_t i = (size_t)blockIdx.x * blockDim.x + threadIdx.x;
    const float4* s = (const float4*)g_partial;
    size_t t = i >> 8;
    size_t c = i & 255;
    size_t base = t * (TOPK * 256) + c;
    float4 a = s[base], b = s[base + 256], cc = s[base + 512], d = s[base + 768];
    ((float4*)out)[i] = make_float4(a.x + b.x + cc.x + d.x,
                                    a.y + b.y + cc.y + d.y,
                                    a.z + b.z + cc.z + d.z,
                                    a.w + b.w + cc.w + d.w);
}

// ---------------- launch ---------------------------------------------------
extern "C" void kernel_launch(void* const* d_in, const int* in_sizes, int n_in,
                              void* d_out, int out_size) {
    const float* x  = (const float*)d_in[0];
    const float* gw = (const float*)d_in[1];
    const float* wg = (const float*)d_in[2];
    const float* wu = (const float*)d_in[3];
    const float* wd = (const float*)d_in[4];
    float* out = (float*)d_out;

    round_x_kernel<<<(T_TOKENS * HDIM / 4) / 256, 256>>>(x);
    transpose_kernel<<<dim3(512, NEXP, 3), 256>>>(wg, wu, wd);

    router_kernel<<<T_TOKENS / 8, 256>>>(x, gw);
    zero_cnt_kernel<<<1, 32>>>();
    scatter_kernel<<<T_TOKENS / 256, 256>>>();
    prefix_kernel<<<1, 32>>>();

    int smem = 2 * STAGE;
    cudaFuncSetAttribute(expert_mma,
                         cudaFuncAttributeMaxDynamicSharedMemorySize, smem);
    expert_mma<<<296, 256, smem>>>(x);

    combine_kernel<<<(T_TOKENS * HDIM / 4) / 256, 256>>>(out);
}

// round 7
// speedup vs baseline: 9.1875x; 1.5568x over previous
#include <cuda_runtime.h>
#include <cuda_fp16.h>
#include <math.h>
#include <stdint.h>

#define T_TOKENS 8192
#define HDIM 1024
#define IDIM 512
#define NEXP 32
#define TOPK 4
#define TILE_M 128
#define KC 64
#define STR 36                 // smem row stride in 4-byte words (144B rows)
#define STAGE 36864            // bytes per pipeline stage
#define WG_OFF 18432
#define WU_OFF 27648
#define WD_OFF 18432

// ---------------- device scratch ----------------
__device__ float  g_partial[(size_t)T_TOKENS * TOPK * HDIM];   // 128 MB fp32
__device__ __half g_hh[(size_t)T_TOKENS * TOPK * IDIM];        // 32 MB
__device__ __half g_xh[(size_t)T_TOKENS * HDIM];               // 16 MB
__device__ __half g_wgh[(size_t)NEXP * IDIM * HDIM];           // 32 MB [E][I][H]
__device__ __half g_wuh[(size_t)NEXP * IDIM * HDIM];           // 32 MB [E][I][H]
__device__ __half g_wdh[(size_t)NEXP * HDIM * IDIM];           // 32 MB [E][H][I]
__device__ int    g_top_idx[T_TOKENS * TOPK];
__device__ float  g_top_wt [T_TOKENS * TOPK];
__device__ int    g_cnt[NEXP];
__device__ int    g_off[NEXP];
__device__ int    g_etok[NEXP * T_TOKENS];
__device__ float  g_ewt [NEXP * T_TOKENS];
__device__ int    g_tiles[2048];
__device__ int    g_ntiles;
__device__ int    g_ticket;
__device__ int    g_done;

// ---------------- helpers ----------------
__device__ __forceinline__ uint32_t smem_u32(const void* p) {
    uint32_t a;
    asm("{ .reg .u64 t; cvta.to.shared.u64 t, %1; cvt.u32.u64 %0, t; }"
        : "=r"(a) : "l"(p));
    return a;
}
__device__ __forceinline__ void cpa16(uint32_t dst, const void* src, int sz) {
    asm volatile("cp.async.ca.shared.global [%0], [%1], 16, %2;"
                 :: "r"(dst), "l"(src), "r"(sz) : "memory");
}
#define CP_COMMIT() asm volatile("cp.async.commit_group;" ::: "memory")
#define CP_WAIT(n)  asm volatile("cp.async.wait_group %0;" :: "n"(n) : "memory")
// fp16 mma, fp32 accumulate: same fragment shape as tf32 m16n8k8 but K=16
#define MMAH(d, a, b)                                                         \
    asm volatile(                                                             \
        "mma.sync.aligned.m16n8k16.row.col.f32.f16.f16.f32 "                  \
        "{%0,%1,%2,%3}, {%4,%5,%6,%7}, {%8,%9}, {%0,%1,%2,%3};"               \
        : "+f"((d)[0]), "+f"((d)[1]), "+f"((d)[2]), "+f"((d)[3])              \
        : "r"((a)[0]), "r"((a)[1]), "r"((a)[2]), "r"((a)[3]),                 \
          "r"((b)[0]), "r"((b)[1]))

// ---------------- prep: x->fp16, weights->fp16 transposed, zero counters ----
__global__ void prep_kernel(const float* __restrict__ x,
                            const float* __restrict__ wg,
                            const float* __restrict__ wu,
                            const float* __restrict__ wd) {
    int sel = blockIdx.z;
    if (sel == 3) {
        if (blockIdx.x == 0 && blockIdx.y == 0 && threadIdx.x < 34) {
            if (threadIdx.x < 32) g_cnt[threadIdx.x] = 0;
            else if (threadIdx.x == 32) g_done = 0;
            else g_ticket = 0;
        }
        size_t i = ((size_t)blockIdx.y * gridDim.x + blockIdx.x) * blockDim.x +
                   threadIdx.x;
        float2 f = ((const float2*)x)[i];
        ((__half2*)g_xh)[i] = __floats2half2_rn(f.x, f.y);
        return;
    }
    __shared__ float t[32][33];
    int e = blockIdx.y;
    int R = (sel == 2) ? IDIM : HDIM;     // src rows
    int C = (sel == 2) ? HDIM : IDIM;     // src cols = dst rows
    int tilesC = C >> 5;
    int r0 = (blockIdx.x / tilesC) << 5;
    int c0 = (blockIdx.x % tilesC) << 5;
    const float* src = ((sel == 0) ? wg : (sel == 1) ? wu : wd) +
                       (size_t)e * HDIM * IDIM;
    __half* dst = ((sel == 0) ? g_wgh : (sel == 1) ? g_wuh : g_wdh) +
                  (size_t)e * HDIM * IDIM;
    int tx = threadIdx.x & 31, ty = threadIdx.x >> 5;
    #pragma unroll
    for (int i = 0; i < 4; ++i)
        t[ty + 8 * i][tx] = src[(size_t)(r0 + ty + 8 * i) * C + c0 + tx];
    __syncthreads();
    #pragma unroll
    for (int i = 0; i < 4; ++i)
        dst[(size_t)(c0 + ty + 8 * i) * R + r0 + tx] =
            __float2half_rn(t[tx][ty + 8 * i]);
}

// ---------------- router: logits -> top-4 ----------------
__global__ void router_kernel(const float* __restrict__ x,
                              const float* __restrict__ gw) {
    __shared__ float xs[8][HDIM];
    int t0 = blockIdx.x * 8;
    for (int i = threadIdx.x; i < 8 * (HDIM / 4); i += blockDim.x) {
        int row = i >> 8;
        int c4  = i & 255;
        ((float4*)xs[row])[c4] = ((const float4*)(x + (size_t)(t0 + row) * HDIM))[c4];
    }
    __syncthreads();

    int w = threadIdx.x >> 5;
    int lane = threadIdx.x & 31;
    int t = t0 + w;
    const float* xr = xs[w];

    float myLogit = 0.f;
    for (int e = 0; e < NEXP; ++e) {
        const float* wr = gw + (size_t)e * HDIM;
        float s = 0.f;
        #pragma unroll 8
        for (int j = lane; j < HDIM; j += 32) s += xr[j] * wr[j];
        #pragma unroll
        for (int off = 16; off; off >>= 1) s += __shfl_xor_sync(0xffffffffu, s, off);
        if (lane == e) myLogit = s;
    }

    float v = myLogit;
    float selv[TOPK];
    int   seli[TOPK];
    #pragma unroll
    for (int k = 0; k < TOPK; ++k) {
        float bv = v; int bi = lane;
        #pragma unroll
        for (int off = 16; off; off >>= 1) {
            float ov = __shfl_xor_sync(0xffffffffu, bv, off);
            int   oi = __shfl_xor_sync(0xffffffffu, bi, off);
            if (ov > bv || (ov == bv && oi < bi)) { bv = ov; bi = oi; }
        }
        selv[k] = bv; seli[k] = bi;
        if (lane == bi) v = -1e30f;
    }

    if (lane == 0) {
        float m = selv[0];
        float ew[TOPK];
        float sum = 0.f;
        #pragma unroll
        for (int k = 0; k < TOPK; ++k) { ew[k] = expf(selv[k] - m); sum += ew[k]; }
        float inv = 1.f / sum;
        #pragma unroll
        for (int k = 0; k < TOPK; ++k) {
            g_top_idx[t * TOPK + k] = seli[k];
            g_top_wt [t * TOPK + k] = ew[k] * inv;
        }
    }
}

// ---------------- scatter + last-block prefix/tile-list ----------------
__global__ void scatter_prefix_kernel() {
    int t = blockIdx.x * blockDim.x + threadIdx.x;
    if (t < T_TOKENS) {
        #pragma unroll
        for (int k = 0; k < TOPK; ++k) {
            int e = g_top_idx[t * TOPK + k];
            int pos = atomicAdd(&g_cnt[e], 1);
            g_etok[e * T_TOKENS + pos] = (t << 2) | k;
            g_ewt [e * T_TOKENS + pos] = g_top_wt[t * TOPK + k];
        }
    }
    __threadfence();
    __syncthreads();
    if (threadIdx.x == 0) {
        int d = atomicAdd(&g_done, 1);
        if (d == (int)gridDim.x - 1) {
            int a = 0, nt = 0;
            for (int e = 0; e < NEXP; ++e) {
                g_off[e] = a;
                int c = *(volatile int*)&g_cnt[e];
                a += c;
                int nt_e = (c + TILE_M - 1) / TILE_M;
                for (int q = 0; q < nt_e; ++q) g_tiles[nt++] = (e << 16) | q;
            }
            g_ntiles = nt;
            g_ticket = 0;
            __threadfence();
        }
    }
}

// ---------------- expert: fp16 mma.sync m16n8k16, cp.async pipeline --------
__global__ void __launch_bounds__(256, 2)
expert_mma() {
    extern __shared__ char sm[];
    __shared__ int   s_tok[TILE_M];
    __shared__ int   s_slot[TILE_M];
    __shared__ float s_wt[TILE_M];
    __shared__ int   s_tile;

    uint32_t smb = smem_u32(sm);
    int tid = threadIdx.x;
    int wid = tid >> 5, lane = tid & 31;
    int gr = lane >> 2, tig = lane & 3;
    int m0 = (wid & 3) * 32;
    int gsel = wid >> 2;
    int n0a = gsel * 32;
    int n0b = gsel * 64;

    for (;;) {
        __syncthreads();
        if (tid == 0) s_tile = atomicAdd(&g_ticket, 1);
        __syncthreads();
        int tI = s_tile;
        if (tI >= g_ntiles) return;
        int pk_t = g_tiles[tI];
        int e = pk_t >> 16;
        int start = (pk_t & 0xffff) * TILE_M;
        int cnt = g_cnt[e];
        int rows = min(TILE_M, cnt - start);

        if (tid < TILE_M) {
            if (tid < rows) {
                int pk = g_etok[e * T_TOKENS + start + tid];
                s_tok[tid] = pk >> 2; s_slot[tid] = pk & 3;
                s_wt[tid] = g_ewt[e * T_TOKENS + start + tid];
            } else { s_tok[tid] = 0; s_slot[tid] = 0; s_wt[tid] = 0.f; }
        }
        __syncthreads();

        const __half* wghE = g_wgh + (size_t)e * HDIM * IDIM;
        const __half* wuhE = g_wuh + (size_t)e * HDIM * IDIM;
        const __half* wdhE = g_wdh + (size_t)e * HDIM * IDIM;
        int hbase = g_off[e] + start;

        // ============== Phase A: h = silu(x Wg) * (x Wu) ==============
        for (int nb = 0; nb < IDIM / 64; ++nb) {
            float accg[2][4][4], accu[2][4][4];
            #pragma unroll
            for (int i = 0; i < 2; ++i)
                #pragma unroll
                for (int j = 0; j < 4; ++j)
                    #pragma unroll
                    for (int q = 0; q < 4; ++q) { accg[i][j][q] = 0.f; accu[i][j][q] = 0.f; }

            #define STAGE_A(c)  do {                                               \
                uint32_t sb = smb + ((c) & 1) * STAGE;                             \
                int k0 = (c) * KC;                                                 \
                _Pragma("unroll")                                                  \
                for (int i2 = 0; i2 < 4; ++i2) {                                   \
                    int idx = tid + i2 * 256;                                      \
                    int m = idx >> 3, seg = idx & 7;                               \
                    cpa16(sb + m * 144 + seg * 16,                                 \
                          g_xh + (size_t)s_tok[m] * HDIM + k0 + seg * 8,           \
                          (m < rows) ? 16 : 0);                                    \
                }                                                                  \
                _Pragma("unroll")                                                  \
                for (int i2 = 0; i2 < 2; ++i2) {                                   \
                    int idx = tid + i2 * 256;                                      \
                    int n = idx >> 3, seg = idx & 7;                               \
                    cpa16(sb + WG_OFF + n * 144 + seg * 16,                        \
                          wghE + (size_t)(nb * 64 + n) * HDIM + k0 + seg * 8, 16); \
                    cpa16(sb + WU_OFF + n * 144 + seg * 16,                        \
                          wuhE + (size_t)(nb * 64 + n) * HDIM + k0 + seg * 8, 16); \
                }                                                                  \
                CP_COMMIT();                                                       \
            } while (0)

            STAGE_A(0);
            for (int c = 0; c < HDIM / KC; ++c) {
                if (c + 1 < HDIM / KC) { STAGE_A(c + 1); CP_WAIT(1); }
                else                   { CP_WAIT(0); }
                __syncthreads();
                const uint32_t* xsu = (const uint32_t*)(sm + (c & 1) * STAGE);
                const uint32_t* wgu = (const uint32_t*)(sm + (c & 1) * STAGE + WG_OFF);
                const uint32_t* wuu = (const uint32_t*)(sm + (c & 1) * STAGE + WU_OFF);
                #pragma unroll
                for (int ks = 0; ks < 4; ++ks) {
                    uint32_t a[2][4];
                    #pragma unroll
                    for (int i = 0; i < 2; ++i) {
                        const uint32_t* p = xsu + (m0 + 16 * i + gr) * STR + ks * 8 + tig;
                        a[i][0] = p[0];
                        a[i][1] = p[8 * STR];
                        a[i][2] = p[4];
                        a[i][3] = p[8 * STR + 4];
                    }
                    #pragma unroll
                    for (int j = 0; j < 4; ++j) {
                        uint32_t bg[2], bu[2];
                        const uint32_t* qg = wgu + (n0a + 8 * j + gr) * STR + ks * 8 + tig;
                        const uint32_t* qu = wuu + (n0a + 8 * j + gr) * STR + ks * 8 + tig;
                        bg[0] = qg[0]; bg[1] = qg[4];
                        bu[0] = qu[0]; bu[1] = qu[4];
                        MMAH(accg[0][j], a[0], bg);
                        MMAH(accg[1][j], a[1], bg);
                        MMAH(accu[0][j], a[0], bu);
                        MMAH(accu[1][j], a[1], bu);
                    }
                }
                __syncthreads();
            }
            #undef STAGE_A

            // epilogue: silu(gate)*up -> g_hh (fp16)
            #pragma unroll
            for (int i = 0; i < 2; ++i) {
                #pragma unroll
                for (int half = 0; half < 2; ++half) {
                    int m = m0 + 16 * i + gr + 8 * half;
                    if (m < rows) {
                        __half* hp = g_hh + (size_t)(hbase + m) * IDIM + nb * 64 + n0a;
                        #pragma unroll
                        for (int j = 0; j < 4; ++j) {
                            float g0 = accg[i][j][half * 2 + 0];
                            float g1 = accg[i][j][half * 2 + 1];
                            float u0 = accu[i][j][half * 2 + 0];
                            float u1 = accu[i][j][half * 2 + 1];
                            float h0 = u0 * g0 / (1.f + __expf(-g0));
                            float h1 = u1 * g1 / (1.f + __expf(-g1));
                            *(__half2*)(hp + 8 * j + 2 * tig) = __floats2half2_rn(h0, h1);
                        }
                    }
                }
            }
            __syncthreads();
        }

        // ============== Phase B: y = (h Wd) * route_w ==============
        for (int nb = 0; nb < HDIM / 128; ++nb) {
            float acc[2][8][4];
            #pragma unroll
            for (int i = 0; i < 2; ++i)
                #pragma unroll
                for (int j = 0; j < 8; ++j)
                    #pragma unroll
                    for (int q = 0; q < 4; ++q) acc[i][j][q] = 0.f;

            #define STAGE_B(c)  do {                                               \
                uint32_t sb = smb + ((c) & 1) * STAGE;                             \
                int k0 = (c) * KC;                                                 \
                _Pragma("unroll")                                                  \
                for (int i2 = 0; i2 < 4; ++i2) {                                   \
                    int idx = tid + i2 * 256;                                      \
                    int m = idx >> 3, seg = idx & 7;                               \
                    cpa16(sb + m * 144 + seg * 16,                                 \
                          g_hh + (size_t)(hbase + m) * IDIM + k0 + seg * 8,        \
                          (m < rows) ? 16 : 0);                                    \
                }                                                                  \
                _Pragma("unroll")                                                  \
                for (int i2 = 0; i2 < 4; ++i2) {                                   \
                    int idx = tid + i2 * 256;                                      \
                    int n = idx >> 3, seg = idx & 7;                               \
                    cpa16(sb + WD_OFF + n * 144 + seg * 16,                        \
                          wdhE + (size_t)(nb * 128 + n) * IDIM + k0 + seg * 8, 16);\
                }                                                                  \
                CP_COMMIT();                                                       \
            } while (0)

            STAGE_B(0);
            for (int c = 0; c < IDIM / KC; ++c) {
                if (c + 1 < IDIM / KC) { STAGE_B(c + 1); CP_WAIT(1); }
                else                   { CP_WAIT(0); }
                __syncthreads();
                const uint32_t* hsu = (const uint32_t*)(sm + (c & 1) * STAGE);
                const uint32_t* wdu = (const uint32_t*)(sm + (c & 1) * STAGE + WD_OFF);
                #pragma unroll
                for (int ks = 0; ks < 4; ++ks) {
                    uint32_t a[2][4];
                    #pragma unroll
                    for (int i = 0; i < 2; ++i) {
                        const uint32_t* p = hsu + (m0 + 16 * i + gr) * STR + ks * 8 + tig;
                        a[i][0] = p[0];
                        a[i][1] = p[8 * STR];
                        a[i][2] = p[4];
                        a[i][3] = p[8 * STR + 4];
                    }
                    #pragma unroll
                    for (int j = 0; j < 8; ++j) {
                        uint32_t b[2];
                        const uint32_t* q = wdu + (n0b + 8 * j + gr) * STR + ks * 8 + tig;
                        b[0] = q[0]; b[1] = q[4];
                        MMAH(acc[0][j], a[0], b);
                        MMAH(acc[1][j], a[1], b);
                    }
                }
                __syncthreads();
            }
            #undef STAGE_B

            // epilogue: apply routing weight, write fp32 partials
            #pragma unroll
            for (int i = 0; i < 2; ++i) {
                #pragma unroll
                for (int half = 0; half < 2; ++half) {
                    int m = m0 + 16 * i + gr + 8 * half;
                    if (m < rows) {
                        float wgt = s_wt[m];
                        float* dp = g_partial +
                            ((size_t)s_tok[m] * TOPK + s_slot[m]) * HDIM + nb * 128 + n0b;
                        #pragma unroll
                        for (int j = 0; j < 8; ++j) {
                            float y0 = wgt * acc[i][j][half * 2 + 0];
                            float y1 = wgt * acc[i][j][half * 2 + 1];
                            *(float2*)(dp + 8 * j + 2 * tig) = make_float2(y0, y1);
                        }
                    }
                }
            }
            __syncthreads();
        }
    }
}

// ---------------- combine: out[t][h] = sum_k partial[t][k][h] -------------
__global__ void combine_kernel(float* __restrict__ out) {
    size_t i = (size_t)blockIdx.x * blockDim.x + threadIdx.x;
    const float4* s = (const float4*)g_partial;
    size_t t = i >> 8;
    size_t c = i & 255;
    size_t base = t * (TOPK * 256) + c;
    float4 a = s[base], b = s[base + 256], cc = s[base + 512], d = s[base + 768];
    ((float4*)out)[i] = make_float4(a.x + b.x + cc.x + d.x,
                                    a.y + b.y + cc.y + d.y,
                                    a.z + b.z + cc.z + d.z,
                                    a.w + b.w + cc.w + d.w);
}

// ---------------- launch ---------------------------------------------------
extern "C" void kernel_launch(void* const* d_in, const int* in_sizes, int n_in,
                              void* d_out, int out_size) {
    const float* x  = (const float*)d_in[0];
    const float* gw = (const float*)d_in[1];
    const float* wg = (const float*)d_in[2];
    const float* wu = (const float*)d_in[3];
    const float* wd = (const float*)d_in[4];
    float* out = (float*)d_out;

    prep_kernel<<<dim3(512, NEXP, 4), 256>>>(x, wg, wu, wd);
    router_kernel<<<T_TOKENS / 8, 256>>>(x, gw);
    scatter_prefix_kernel<<<T_TOKENS / 256, 256>>>();

    int smem = 2 * STAGE;
    cudaFuncSetAttribute(expert_mma,
                         cudaFuncAttributeMaxDynamicSharedMemorySize, smem);
    expert_mma<<<296, 256, smem>>>();

    combine_kernel<<<(T_TOKENS * HDIM / 4) / 256, 256>>>(out);
}

// round 8
// speedup vs baseline: 9.4838x; 1.0322x over previous
#include <cuda_runtime.h>
#include <cuda_fp16.h>
#include <math.h>
#include <stdint.h>

#define T_TOKENS 8192
#define HDIM 1024
#define IDIM 512
#define NEXP 32
#define TOPK 4
#define TILE_M 128
#define KC 64
#define STAGE 36864            // bytes per pipeline stage (rows of 144B)
#define NSTAGE 3
#define WG_OFF 18432
#define WU_OFF 27648
#define WD_OFF 18432

// ---------------- device scratch ----------------
__device__ float  g_partial[(size_t)T_TOKENS * TOPK * HDIM];   // 128 MB fp32
__device__ __half g_hh[(size_t)T_TOKENS * TOPK * IDIM];        // 32 MB
__device__ __half g_xh[(size_t)T_TOKENS * HDIM];               // 16 MB
__device__ __half g_wgh[(size_t)NEXP * IDIM * HDIM];           // 32 MB [E][I][H]
__device__ __half g_wuh[(size_t)NEXP * IDIM * HDIM];           // 32 MB [E][I][H]
__device__ __half g_wdh[(size_t)NEXP * HDIM * IDIM];           // 32 MB [E][H][I]
__device__ int    g_top_idx[T_TOKENS * TOPK];
__device__ float  g_top_wt [T_TOKENS * TOPK];
__device__ int    g_cnt[NEXP];
__device__ int    g_off[NEXP];
__device__ int    g_etok[NEXP * T_TOKENS];
__device__ float  g_ewt [NEXP * T_TOKENS];
__device__ int    g_tiles[2048];
__device__ int    g_ntiles;
__device__ int    g_ticket;
__device__ int    g_done;

// ---------------- helpers ----------------
__device__ __forceinline__ uint32_t smem_u32(const void* p) {
    uint32_t a;
    asm("{ .reg .u64 t; cvta.to.shared.u64 t, %1; cvt.u32.u64 %0, t; }"
        : "=r"(a) : "l"(p));
    return a;
}
__device__ __forceinline__ void cpa16(uint32_t dst, const void* src, int sz) {
    asm volatile("cp.async.ca.shared.global [%0], [%1], 16, %2;"
                 :: "r"(dst), "l"(src), "r"(sz) : "memory");
}
#define CP_COMMIT() asm volatile("cp.async.commit_group;" ::: "memory")
#define CP_WAIT(n)  asm volatile("cp.async.wait_group %0;" :: "n"(n) : "memory")
#define MMAH(d, a0, a1, a2, a3, b0, b1)                                       \
    asm volatile(                                                             \
        "mma.sync.aligned.m16n8k16.row.col.f32.f16.f16.f32 "                  \
        "{%0,%1,%2,%3}, {%4,%5,%6,%7}, {%8,%9}, {%0,%1,%2,%3};"               \
        : "+f"((d)[0]), "+f"((d)[1]), "+f"((d)[2]), "+f"((d)[3])              \
        : "r"(a0), "r"(a1), "r"(a2), "r"(a3), "r"(b0), "r"(b1))
#define LDM4(R, addr)                                                         \
    asm volatile("ldmatrix.sync.aligned.m8n8.x4.shared.b16 {%0,%1,%2,%3}, [%4];" \
        : "=r"((R)[0]), "=r"((R)[1]), "=r"((R)[2]), "=r"((R)[3])              \
        : "r"(addr))

// ---------------- prep: x->fp16, weights->fp16 transposed, zero counters ----
__global__ void prep_kernel(const float* __restrict__ x,
                            const float* __restrict__ wg,
                            const float* __restrict__ wu,
                            const float* __restrict__ wd) {
    int sel = blockIdx.z;
    if (sel == 3) {
        if (blockIdx.x == 0 && blockIdx.y == 0 && threadIdx.x < 34) {
            if (threadIdx.x < 32) g_cnt[threadIdx.x] = 0;
            else if (threadIdx.x == 32) g_done = 0;
            else g_ticket = 0;
        }
        size_t i = ((size_t)blockIdx.y * gridDim.x + blockIdx.x) * blockDim.x +
                   threadIdx.x;
        float2 f = ((const float2*)x)[i];
        ((__half2*)g_xh)[i] = __floats2half2_rn(f.x, f.y);
        return;
    }
    __shared__ float t[32][33];
    int e = blockIdx.y;
    int R = (sel == 2) ? IDIM : HDIM;     // src rows
    int C = (sel == 2) ? HDIM : IDIM;     // src cols = dst rows
    int tilesC = C >> 5;
    int r0 = (blockIdx.x / tilesC) << 5;
    int c0 = (blockIdx.x % tilesC) << 5;
    const float* src = ((sel == 0) ? wg : (sel == 1) ? wu : wd) +
                       (size_t)e * HDIM * IDIM;
    __half* dst = ((sel == 0) ? g_wgh : (sel == 1) ? g_wuh : g_wdh) +
                  (size_t)e * HDIM * IDIM;
    int tx = threadIdx.x & 31, ty = threadIdx.x >> 5;
    #pragma unroll
    for (int i = 0; i < 4; ++i)
        t[ty + 8 * i][tx] = src[(size_t)(r0 + ty + 8 * i) * C + c0 + tx];
    __syncthreads();
    #pragma unroll
    for (int i = 0; i < 4; ++i)
        dst[(size_t)(c0 + ty + 8 * i) * R + r0 + tx] =
            __float2half_rn(t[tx][ty + 8 * i]);
}

// ---------------- router: logits -> top-4 ----------------
__global__ void router_kernel(const float* __restrict__ x,
                              const float* __restrict__ gw) {
    __shared__ float xs[8][HDIM];
    int t0 = blockIdx.x * 8;
    for (int i = threadIdx.x; i < 8 * (HDIM / 4); i += blockDim.x) {
        int row = i >> 8;
        int c4  = i & 255;
        ((float4*)xs[row])[c4] = ((const float4*)(x + (size_t)(t0 + row) * HDIM))[c4];
    }
    __syncthreads();

    int w = threadIdx.x >> 5;
    int lane = threadIdx.x & 31;
    int t = t0 + w;
    const float* xr = xs[w];

    float myLogit = 0.f;
    for (int e = 0; e < NEXP; ++e) {
        const float* wr = gw + (size_t)e * HDIM;
        float s = 0.f;
        #pragma unroll 8
        for (int j = lane; j < HDIM; j += 32) s += xr[j] * wr[j];
        #pragma unroll
        for (int off = 16; off; off >>= 1) s += __shfl_xor_sync(0xffffffffu, s, off);
        if (lane == e) myLogit = s;
    }

    float v = myLogit;
    float selv[TOPK];
    int   seli[TOPK];
    #pragma unroll
    for (int k = 0; k < TOPK; ++k) {
        float bv = v; int bi = lane;
        #pragma unroll
        for (int off = 16; off; off >>= 1) {
            float ov = __shfl_xor_sync(0xffffffffu, bv, off);
            int   oi = __shfl_xor_sync(0xffffffffu, bi, off);
            if (ov > bv || (ov == bv && oi < bi)) { bv = ov; bi = oi; }
        }
        selv[k] = bv; seli[k] = bi;
        if (lane == bi) v = -1e30f;
    }

    if (lane == 0) {
        float m = selv[0];
        float ew[TOPK];
        float sum = 0.f;
        #pragma unroll
        for (int k = 0; k < TOPK; ++k) { ew[k] = expf(selv[k] - m); sum += ew[k]; }
        float inv = 1.f / sum;
        #pragma unroll
        for (int k = 0; k < TOPK; ++k) {
            g_top_idx[t * TOPK + k] = seli[k];
            g_top_wt [t * TOPK + k] = ew[k] * inv;
        }
    }
}

// ---------------- scatter + last-block prefix/tile-list ----------------
__global__ void scatter_prefix_kernel() {
    int t = blockIdx.x * blockDim.x + threadIdx.x;
    if (t < T_TOKENS) {
        #pragma unroll
        for (int k = 0; k < TOPK; ++k) {
            int e = g_top_idx[t * TOPK + k];
            int pos = atomicAdd(&g_cnt[e], 1);
            g_etok[e * T_TOKENS + pos] = (t << 2) | k;
            g_ewt [e * T_TOKENS + pos] = g_top_wt[t * TOPK + k];
        }
    }
    __threadfence();
    __syncthreads();
    if (threadIdx.x == 0) {
        int d = atomicAdd(&g_done, 1);
        if (d == (int)gridDim.x - 1) {
            int a = 0, nt = 0;
            for (int e = 0; e < NEXP; ++e) {
                g_off[e] = a;
                int c = *(volatile int*)&g_cnt[e];
                a += c;
                int nt_e = (c + TILE_M - 1) / TILE_M;
                for (int q = 0; q < nt_e; ++q) g_tiles[nt++] = (e << 16) | q;
            }
            g_ntiles = nt;
            g_ticket = 0;
            __threadfence();
        }
    }
}

// ---------------- expert: fp16 mma + ldmatrix + 3-stage cp.async -----------
__global__ void __launch_bounds__(256, 2)
expert_mma() {
    extern __shared__ char sm[];
    __shared__ int   s_tok[TILE_M];
    __shared__ int   s_slot[TILE_M];
    __shared__ float s_wt[TILE_M];
    __shared__ int   s_tile;

    uint32_t smb = smem_u32(sm);
    int tid = threadIdx.x;
    int wid = tid >> 5, lane = tid & 31;
    int gr = lane >> 2, tig = lane & 3;
    int m0 = (wid & 3) * 32;
    int gsel = wid >> 2;
    int n0a = gsel * 32;
    int n0b = gsel * 64;

    // ldmatrix per-lane address components (within a stage buffer)
    int lrowA = lane & 15;                       // A: row within 16-row subtile
    int lkA   = (lane >> 4) * 16;                // A: 16B k-offset
    int lrowB = ((lane >> 4) << 3) + (lane & 7); // B: row within 16-row pair
    int lkB   = (lane & 8) ? 16 : 0;             // B: 16B k-offset
    uint32_t aoff  = (uint32_t)(m0 + lrowA) * 144 + lkA;
    uint32_t gboff = (uint32_t)WG_OFF + (uint32_t)(n0a + lrowB) * 144 + lkB;
    uint32_t uboff = (uint32_t)WU_OFF + (uint32_t)(n0a + lrowB) * 144 + lkB;
    uint32_t dboff = (uint32_t)WD_OFF + (uint32_t)(n0b + lrowB) * 144 + lkB;

    for (;;) {
        __syncthreads();
        if (tid == 0) s_tile = atomicAdd(&g_ticket, 1);
        __syncthreads();
        int tI = s_tile;
        if (tI >= g_ntiles) return;
        int pk_t = g_tiles[tI];
        int e = pk_t >> 16;
        int start = (pk_t & 0xffff) * TILE_M;
        int cnt = g_cnt[e];
        int rows = min(TILE_M, cnt - start);

        if (tid < TILE_M) {
            if (tid < rows) {
                int pk = g_etok[e * T_TOKENS + start + tid];
                s_tok[tid] = pk >> 2; s_slot[tid] = pk & 3;
                s_wt[tid] = g_ewt[e * T_TOKENS + start + tid];
            } else { s_tok[tid] = 0; s_slot[tid] = 0; s_wt[tid] = 0.f; }
        }
        __syncthreads();

        const __half* wghE = g_wgh + (size_t)e * HDIM * IDIM;
        const __half* wuhE = g_wuh + (size_t)e * HDIM * IDIM;
        const __half* wdhE = g_wdh + (size_t)e * HDIM * IDIM;
        int hbase = g_off[e] + start;

        // ============== Phase A: h = silu(x Wg) * (x Wu) ==============
        for (int nb = 0; nb < IDIM / 64; ++nb) {
            float accg[2][4][4], accu[2][4][4];
            #pragma unroll
            for (int i = 0; i < 2; ++i)
                #pragma unroll
                for (int j = 0; j < 4; ++j)
                    #pragma unroll
                    for (int q = 0; q < 4; ++q) { accg[i][j][q] = 0.f; accu[i][j][q] = 0.f; }

            #define STAGE_A(c)  do {                                               \
                uint32_t sb = smb + ((c) % NSTAGE) * STAGE;                        \
                int k0 = (c) * KC;                                                 \
                _Pragma("unroll")                                                  \
                for (int i2 = 0; i2 < 4; ++i2) {                                   \
                    int idx = tid + i2 * 256;                                      \
                    int m = idx >> 3, seg = idx & 7;                               \
                    cpa16(sb + m * 144 + seg * 16,                                 \
                          g_xh + (size_t)s_tok[m] * HDIM + k0 + seg * 8,           \
                          (m < rows) ? 16 : 0);                                    \
                }                                                                  \
                _Pragma("unroll")                                                  \
                for (int i2 = 0; i2 < 2; ++i2) {                                   \
                    int idx = tid + i2 * 256;                                      \
                    int n = idx >> 3, seg = idx & 7;                               \
                    cpa16(sb + WG_OFF + n * 144 + seg * 16,                        \
                          wghE + (size_t)(nb * 64 + n) * HDIM + k0 + seg * 8, 16); \
                    cpa16(sb + WU_OFF + n * 144 + seg * 16,                        \
                          wuhE + (size_t)(nb * 64 + n) * HDIM + k0 + seg * 8, 16); \
                }                                                                  \
                CP_COMMIT();                                                       \
            } while (0)

            STAGE_A(0);
            STAGE_A(1);
            for (int c = 0; c < HDIM / KC; ++c) {
                CP_WAIT(1);
                __syncthreads();
                uint32_t sb = smb + (c % NSTAGE) * STAGE;
                #pragma unroll
                for (int ks = 0; ks < 4; ++ks) {
                    uint32_t a[2][4];
                    LDM4(a[0], sb + aoff + ks * 32);
                    LDM4(a[1], sb + aoff + 2304 + ks * 32);
                    #pragma unroll
                    for (int p = 0; p < 2; ++p) {
                        uint32_t bg[4], bu[4];
                        LDM4(bg, sb + gboff + p * 2304 + ks * 32);
                        LDM4(bu, sb + uboff + p * 2304 + ks * 32);
                        MMAH(accg[0][2*p],   a[0][0], a[0][1], a[0][2], a[0][3], bg[0], bg[1]);
                        MMAH(accg[1][2*p],   a[1][0], a[1][1], a[1][2], a[1][3], bg[0], bg[1]);
                        MMAH(accg[0][2*p+1], a[0][0], a[0][1], a[0][2], a[0][3], bg[2], bg[3]);
                        MMAH(accg[1][2*p+1], a[1][0], a[1][1], a[1][2], a[1][3], bg[2], bg[3]);
                        MMAH(accu[0][2*p],   a[0][0], a[0][1], a[0][2], a[0][3], bu[0], bu[1]);
                        MMAH(accu[1][2*p],   a[1][0], a[1][1], a[1][2], a[1][3], bu[0], bu[1]);
                        MMAH(accu[0][2*p+1], a[0][0], a[0][1], a[0][2], a[0][3], bu[2], bu[3]);
                        MMAH(accu[1][2*p+1], a[1][0], a[1][1], a[1][2], a[1][3], bu[2], bu[3]);
                    }
                }
                if (c + 2 < HDIM / KC) STAGE_A(c + 2);
                else CP_COMMIT();
            }
            #undef STAGE_A

            // epilogue: silu(gate)*up -> g_hh (fp16)
            #pragma unroll
            for (int i = 0; i < 2; ++i) {
                #pragma unroll
                for (int half = 0; half < 2; ++half) {
                    int m = m0 + 16 * i + gr + 8 * half;
                    if (m < rows) {
                        __half* hp = g_hh + (size_t)(hbase + m) * IDIM + nb * 64 + n0a;
                        #pragma unroll
                        for (int j = 0; j < 4; ++j) {
                            float g0 = accg[i][j][half * 2 + 0];
                            float g1 = accg[i][j][half * 2 + 1];
                            float u0 = accu[i][j][half * 2 + 0];
                            float u1 = accu[i][j][half * 2 + 1];
                            float h0 = u0 * g0 / (1.f + __expf(-g0));
                            float h1 = u1 * g1 / (1.f + __expf(-g1));
                            *(__half2*)(hp + 8 * j + 2 * tig) = __floats2half2_rn(h0, h1);
                        }
                    }
                }
            }
            __syncthreads();
        }

        // ============== Phase B: y = (h Wd) * route_w ==============
        for (int nb = 0; nb < HDIM / 128; ++nb) {
            float acc[2][8][4];
            #pragma unroll
            for (int i = 0; i < 2; ++i)
                #pragma unroll
                for (int j = 0; j < 8; ++j)
                    #pragma unroll
                    for (int q = 0; q < 4; ++q) acc[i][j][q] = 0.f;

            #define STAGE_B(c)  do {                                               \
                uint32_t sb = smb + ((c) % NSTAGE) * STAGE;                        \
                int k0 = (c) * KC;                                                 \
                _Pragma("unroll")                                                  \
                for (int i2 = 0; i2 < 4; ++i2) {                                   \
                    int idx = tid + i2 * 256;                                      \
                    int m = idx >> 3, seg = idx & 7;                               \
                    cpa16(sb + m * 144 + seg * 16,                                 \
                          g_hh + (size_t)(hbase + m) * IDIM + k0 + seg * 8,        \
                          (m < rows) ? 16 : 0);                                    \
                }                                                                  \
                _Pragma("unroll")                                                  \
                for (int i2 = 0; i2 < 4; ++i2) {                                   \
                    int idx = tid + i2 * 256;                                      \
                    int n = idx >> 3, seg = idx & 7;                               \
                    cpa16(sb + WD_OFF + n * 144 + seg * 16,                        \
                          wdhE + (size_t)(nb * 128 + n) * IDIM + k0 + seg * 8, 16);\
                }                                                                  \
                CP_COMMIT();                                                       \
            } while (0)

            STAGE_B(0);
            STAGE_B(1);
            for (int c = 0; c < IDIM / KC; ++c) {
                CP_WAIT(1);
                __syncthreads();
                uint32_t sb = smb + (c % NSTAGE) * STAGE;
                #pragma unroll
                for (int ks = 0; ks < 4; ++ks) {
                    uint32_t a[2][4];
                    LDM4(a[0], sb + aoff + ks * 32);
                    LDM4(a[1], sb + aoff + 2304 + ks * 32);
                    #pragma unroll
                    for (int p = 0; p < 4; ++p) {
                        uint32_t b[4];
                        LDM4(b, sb + dboff + p * 2304 + ks * 32);
                        MMAH(acc[0][2*p],   a[0][0], a[0][1], a[0][2], a[0][3], b[0], b[1]);
                        MMAH(acc[1][2*p],   a[1][0], a[1][1], a[1][2], a[1][3], b[0], b[1]);
                        MMAH(acc[0][2*p+1], a[0][0], a[0][1], a[0][2], a[0][3], b[2], b[3]);
                        MMAH(acc[1][2*p+1], a[1][0], a[1][1], a[1][2], a[1][3], b[2], b[3]);
                    }
                }
                if (c + 2 < IDIM / KC) STAGE_B(c + 2);
                else CP_COMMIT();
            }
            #undef STAGE_B

            // epilogue: apply routing weight, write fp32 partials
            #pragma unroll
            for (int i = 0; i < 2; ++i) {
                #pragma unroll
                for (int half = 0; half < 2; ++half) {
                    int m = m0 + 16 * i + gr + 8 * half;
                    if (m < rows) {
                        float wgt = s_wt[m];
                        float* dp = g_partial +
                            ((size_t)s_tok[m] * TOPK + s_slot[m]) * HDIM + nb * 128 + n0b;
                        #pragma unroll
                        for (int j = 0; j < 8; ++j) {
                            float y0 = wgt * acc[i][j][half * 2 + 0];
                            float y1 = wgt * acc[i][j][half * 2 + 1];
                            *(float2*)(dp + 8 * j + 2 * tig) = make_float2(y0, y1);
                        }
                    }
                }
            }
            __syncthreads();
        }
    }
}

// ---------------- combine: out[t][h] = sum_k partial[t][k][h] -------------
__global__ void combine_kernel(float* __restrict__ out) {
    size_t i = (size_t)blockIdx.x * blockDim.x + threadIdx.x;
    const float4* s = (const float4*)g_partial;
    size_t t = i >> 8;
    size_t c = i & 255;
    size_t base = t * (TOPK * 256) + c;
    float4 a = s[base], b = s[base + 256], cc = s[base + 512], d = s[base + 768];
    ((float4*)out)[i] = make_float4(a.x + b.x + cc.x + d.x,
                                    a.y + b.y + cc.y + d.y,
                                    a.z + b.z + cc.z + d.z,
                                    a.w + b.w + cc.w + d.w);
}

// ---------------- launch ---------------------------------------------------
extern "C" void kernel_launch(void* const* d_in, const int* in_sizes, int n_in,
                              void* d_out, int out_size) {
    const float* x  = (const float*)d_in[0];
    const float* gw = (const float*)d_in[1];
    const float* wg = (const float*)d_in[2];
    const float* wu = (const float*)d_in[3];
    const float* wd = (const float*)d_in[4];
    float* out = (float*)d_out;

    prep_kernel<<<dim3(512, NEXP, 4), 256>>>(x, wg, wu, wd);
    router_kernel<<<T_TOKENS / 8, 256>>>(x, gw);
    scatter_prefix_kernel<<<T_TOKENS / 256, 256>>>();

    int smem = NSTAGE * STAGE;
    cudaFuncSetAttribute(expert_mma,
                         cudaFuncAttributeMaxDynamicSharedMemorySize, smem);
    expert_mma<<<296, 256, smem>>>();

    combine_kernel<<<(T_TOKENS * HDIM / 4) / 256, 256>>>(out);
}